// round 7
// baseline (speedup 1.0000x reference)
#include <cuda_runtime.h>
#include <cstdint>

// Problem constants (shapes are fixed by the dataset; runtime n/e still honored)
#define NMAX 100000
#define DDIM 64
#define EPS_BN 1e-5f

// Scratch (device globals: no allocation allowed in kernel_launch)
__device__ float g_z[NMAX * DDIM];   // z = x @ W^T
__device__ float g_h[NMAX * DDIM];   // h = x + b + A @ z   (pre-BN activations)
__device__ float g_sum[DDIM];
__device__ float g_sumsq[DDIM];

// ---------------------------------------------------------------------------
// K1: h = x + b (fold residual + bias); also zero the BN stat accumulators
// ---------------------------------------------------------------------------
__global__ void k_init(const float* __restrict__ x, const float* __restrict__ b, int n)
{
    if (blockIdx.x == 0 && threadIdx.x < 2 * DDIM) {
        if (threadIdx.x < DDIM) g_sum[threadIdx.x] = 0.f;
        else                    g_sumsq[threadIdx.x - DDIM] = 0.f;
    }
    int idx = blockIdx.x * blockDim.x + threadIdx.x;   // over n*16 float4
    int total = n * (DDIM / 4);
    if (idx < total) {
        float4 xv = reinterpret_cast<const float4*>(x)[idx];
        int d0 = (idx & 15) * 4;
        float4 hv;
        hv.x = xv.x + b[d0 + 0];
        hv.y = xv.y + b[d0 + 1];
        hv.z = xv.z + b[d0 + 2];
        hv.w = xv.w + b[d0 + 3];
        reinterpret_cast<float4*>(g_h)[idx] = hv;
    }
}

// ---------------------------------------------------------------------------
// K2: z = x @ W^T.  One thread per row; W (16KB) in smem, broadcast LDS.128.
// ---------------------------------------------------------------------------
__global__ void __launch_bounds__(128) k_gemm(const float* __restrict__ x,
                                              const float* __restrict__ W, int n)
{
    __shared__ float4 Ws[DDIM * 16];            // W[o][k] as float4 over k
    for (int i = threadIdx.x; i < DDIM * 16; i += 128)
        Ws[i] = reinterpret_cast<const float4*>(W)[i];
    __syncthreads();

    int row = blockIdx.x * 128 + threadIdx.x;
    if (row >= n) return;

    const float4* x4 = reinterpret_cast<const float4*>(x);
    float4 xr[16];
#pragma unroll
    for (int i = 0; i < 16; i++) xr[i] = x4[row * 16 + i];

    float4* z4 = reinterpret_cast<float4*>(g_z);
#pragma unroll 1
    for (int og = 0; og < 16; og++) {          // 4 output columns per iter
        float4 acc = make_float4(0.f, 0.f, 0.f, 0.f);
#pragma unroll
        for (int k4 = 0; k4 < 16; k4++) {
            float4 xv = xr[k4];
            float4 w0 = Ws[(4 * og + 0) * 16 + k4];
            float4 w1 = Ws[(4 * og + 1) * 16 + k4];
            float4 w2 = Ws[(4 * og + 2) * 16 + k4];
            float4 w3 = Ws[(4 * og + 3) * 16 + k4];
            acc.x += xv.x * w0.x + xv.y * w0.y + xv.z * w0.z + xv.w * w0.w;
            acc.y += xv.x * w1.x + xv.y * w1.y + xv.z * w1.z + xv.w * w1.w;
            acc.z += xv.x * w2.x + xv.y * w2.y + xv.z * w2.z + xv.w * w2.w;
            acc.w += xv.x * w3.x + xv.y * w3.y + xv.z * w3.z + xv.w * w3.w;
        }
        z4[row * 16 + og] = acc;
    }
}

// ---------------------------------------------------------------------------
// K3: edge scatter  h[row] += val * z[col]   (16 threads per edge, red.v4.f32)
// ---------------------------------------------------------------------------
__global__ void k_scatter(const float* __restrict__ val,
                          const int* __restrict__ row,
                          const int* __restrict__ col, int e)
{
    int g = blockIdx.x * blockDim.x + threadIdx.x;
    int eid = g >> 4;
    if (eid >= e) return;
    int l = g & 15;

    float v = __ldg(&val[eid]);
    int r = __ldg(&row[eid]);
    int c = __ldg(&col[eid]);

    float4 zv = reinterpret_cast<const float4*>(g_z)[c * 16 + l];
    float ax = v * zv.x, ay = v * zv.y, az = v * zv.z, aw = v * zv.w;
    float* dst = g_h + (size_t)r * DDIM + l * 4;
    asm volatile("red.global.add.v4.f32 [%0], {%1,%2,%3,%4};"
                 :: "l"(dst), "f"(ax), "f"(ay), "f"(az), "f"(aw) : "memory");
}

// ---------------------------------------------------------------------------
// K4: per-column sum and sum-of-squares of h
// ---------------------------------------------------------------------------
__global__ void __launch_bounds__(256) k_stats(int n)
{
    int cg = threadIdx.x & 15;                 // column group (4 cols)
    float4 s  = make_float4(0.f, 0.f, 0.f, 0.f);
    float4 ss = make_float4(0.f, 0.f, 0.f, 0.f);
    const float4* h4 = reinterpret_cast<const float4*>(g_h);
    int total = n * 16;
    int stride = gridDim.x * blockDim.x;       // multiple of 16 -> cg invariant
    for (int idx = blockIdx.x * blockDim.x + threadIdx.x; idx < total; idx += stride) {
        float4 v = h4[idx];
        s.x += v.x; s.y += v.y; s.z += v.z; s.w += v.w;
        ss.x += v.x * v.x; ss.y += v.y * v.y; ss.z += v.z * v.z; ss.w += v.w * v.w;
    }
    __shared__ float4 sh_s[256];
    __shared__ float4 sh_q[256];
    sh_s[threadIdx.x] = s;
    sh_q[threadIdx.x] = ss;
    __syncthreads();
#pragma unroll
    for (int off = 128; off >= 16; off >>= 1) {
        if (threadIdx.x < off) {
            float4 a = sh_s[threadIdx.x], b = sh_s[threadIdx.x + off];
            a.x += b.x; a.y += b.y; a.z += b.z; a.w += b.w;
            sh_s[threadIdx.x] = a;
            float4 c = sh_q[threadIdx.x], d = sh_q[threadIdx.x + off];
            c.x += d.x; c.y += d.y; c.z += d.z; c.w += d.w;
            sh_q[threadIdx.x] = c;
        }
        __syncthreads();
    }
    if (threadIdx.x < 16) {
        float4 a = sh_s[threadIdx.x];
        float4 c = sh_q[threadIdx.x];
        int d0 = cg * 4;
        atomicAdd(&g_sum[d0 + 0], a.x);  atomicAdd(&g_sum[d0 + 1], a.y);
        atomicAdd(&g_sum[d0 + 2], a.z);  atomicAdd(&g_sum[d0 + 3], a.w);
        atomicAdd(&g_sumsq[d0 + 0], c.x); atomicAdd(&g_sumsq[d0 + 1], c.y);
        atomicAdd(&g_sumsq[d0 + 2], c.z); atomicAdd(&g_sumsq[d0 + 3], c.w);
    }
}

// ---------------------------------------------------------------------------
// K5: out = relu((h - mean) * rsqrt(var+eps) * gamma + beta)
//     (scale/shift recomputed per block from the 64 global sums — cheap)
// ---------------------------------------------------------------------------
__global__ void k_norm(const float* __restrict__ gamma,
                       const float* __restrict__ beta,
                       float* __restrict__ out, int n)
{
    __shared__ float sc[DDIM];
    __shared__ float sh[DDIM];
    if (threadIdx.x < DDIM) {
        int d = threadIdx.x;
        float inv = 1.0f / (float)n;
        float mean = g_sum[d] * inv;
        float var  = g_sumsq[d] * inv - mean * mean;
        float s = gamma[d] * rsqrtf(var + EPS_BN);
        sc[d] = s;
        sh[d] = beta[d] - mean * s;
    }
    __syncthreads();
    int idx = blockIdx.x * blockDim.x + threadIdx.x;
    int total = n * 16;
    if (idx < total) {
        float4 v = reinterpret_cast<const float4*>(g_h)[idx];
        int d0 = (idx & 15) * 4;
        float4 o;
        o.x = fmaxf(v.x * sc[d0 + 0] + sh[d0 + 0], 0.f);
        o.y = fmaxf(v.y * sc[d0 + 1] + sh[d0 + 1], 0.f);
        o.z = fmaxf(v.z * sc[d0 + 2] + sh[d0 + 2], 0.f);
        o.w = fmaxf(v.w * sc[d0 + 3] + sh[d0 + 3], 0.f);
        reinterpret_cast<float4*>(out)[idx] = o;
    }
}

// ---------------------------------------------------------------------------
// Launch: inputs in metadata order:
//   0 x [N*64] f32, 1 adj_val [E] f32, 2 W [64*64] f32, 3 b [64] f32,
//   4 gamma [64] f32, 5 beta [64] f32, 6 adj_row [E] i32, 7 adj_col [E] i32
// ---------------------------------------------------------------------------
extern "C" void kernel_launch(void* const* d_in, const int* in_sizes, int n_in,
                              void* d_out, int out_size)
{
    const float* x       = (const float*)d_in[0];
    const float* adj_val = (const float*)d_in[1];
    const float* W       = (const float*)d_in[2];
    const float* b       = (const float*)d_in[3];
    const float* gamma   = (const float*)d_in[4];
    const float* beta    = (const float*)d_in[5];
    const int*   adj_row = (const int*)d_in[6];
    const int*   adj_col = (const int*)d_in[7];
    float* out = (float*)d_out;

    int n = in_sizes[0] / DDIM;    // 100000
    int e = in_sizes[1];           // 1600000
    int nv = n * (DDIM / 4);       // float4 count

    k_init   <<<(nv + 255) / 256, 256>>>(x, b, n);
    k_gemm   <<<(n + 127) / 128, 128>>>(x, W, n);
    k_scatter<<<((long)e * 16 + 255) / 256, 256>>>(adj_val, adj_row, adj_col, e);
    k_stats  <<<1184, 256>>>(n);
    k_norm   <<<(nv + 255) / 256, 256>>>(gamma, beta, out, n);
}

// round 8
// speedup vs baseline: 1.0100x; 1.0100x over previous
#include <cuda_runtime.h>
#include <cstdint>

// Problem constants (shapes are fixed by the dataset; runtime n/e still honored)
#define NMAX 100000
#define DDIM 64
#define EPS_BN 1e-5f

// Scratch (device globals: no allocation allowed in kernel_launch)
__device__ float g_z[NMAX * DDIM];   // z = x @ W^T
__device__ float g_h[NMAX * DDIM];   // h = x + b + A @ z   (pre-BN activations)
__device__ float g_sum[DDIM];
__device__ float g_sumsq[DDIM];

// ---------------------------------------------------------------------------
// K1: h = x + b (fold residual + bias); also zero the BN stat accumulators
// ---------------------------------------------------------------------------
__global__ void k_init(const float* __restrict__ x, const float* __restrict__ b, int n)
{
    if (blockIdx.x == 0 && threadIdx.x < 2 * DDIM) {
        if (threadIdx.x < DDIM) g_sum[threadIdx.x] = 0.f;
        else                    g_sumsq[threadIdx.x - DDIM] = 0.f;
    }
    int idx = blockIdx.x * blockDim.x + threadIdx.x;   // over n*16 float4
    int total = n * (DDIM / 4);
    if (idx < total) {
        float4 xv = reinterpret_cast<const float4*>(x)[idx];
        int d0 = (idx & 15) * 4;
        float4 hv;
        hv.x = xv.x + b[d0 + 0];
        hv.y = xv.y + b[d0 + 1];
        hv.z = xv.z + b[d0 + 2];
        hv.w = xv.w + b[d0 + 3];
        reinterpret_cast<float4*>(g_h)[idx] = hv;
    }
}

// ---------------------------------------------------------------------------
// K2: z = x @ W^T.  One thread per row; W (16KB) in smem, broadcast LDS.128.
// ---------------------------------------------------------------------------
__global__ void __launch_bounds__(128) k_gemm(const float* __restrict__ x,
                                              const float* __restrict__ W, int n)
{
    __shared__ float4 Ws[DDIM * 16];            // W[o][k] as float4 over k
    for (int i = threadIdx.x; i < DDIM * 16; i += 128)
        Ws[i] = reinterpret_cast<const float4*>(W)[i];
    __syncthreads();

    int row = blockIdx.x * 128 + threadIdx.x;
    if (row >= n) return;

    const float4* x4 = reinterpret_cast<const float4*>(x);
    float4 xr[16];
#pragma unroll
    for (int i = 0; i < 16; i++) xr[i] = x4[row * 16 + i];

    float4* z4 = reinterpret_cast<float4*>(g_z);
#pragma unroll 1
    for (int og = 0; og < 16; og++) {          // 4 output columns per iter
        float4 acc = make_float4(0.f, 0.f, 0.f, 0.f);
#pragma unroll
        for (int k4 = 0; k4 < 16; k4++) {
            float4 xv = xr[k4];
            float4 w0 = Ws[(4 * og + 0) * 16 + k4];
            float4 w1 = Ws[(4 * og + 1) * 16 + k4];
            float4 w2 = Ws[(4 * og + 2) * 16 + k4];
            float4 w3 = Ws[(4 * og + 3) * 16 + k4];
            acc.x += xv.x * w0.x + xv.y * w0.y + xv.z * w0.z + xv.w * w0.w;
            acc.y += xv.x * w1.x + xv.y * w1.y + xv.z * w1.z + xv.w * w1.w;
            acc.z += xv.x * w2.x + xv.y * w2.y + xv.z * w2.z + xv.w * w2.w;
            acc.w += xv.x * w3.x + xv.y * w3.y + xv.z * w3.z + xv.w * w3.w;
        }
        z4[row * 16 + og] = acc;
    }
}

// ---------------------------------------------------------------------------
// K3: edge scatter  h[row] += val * z[col]   (16 threads per edge, red.v4.f32)
// ---------------------------------------------------------------------------
__global__ void k_scatter(const float* __restrict__ val,
                          const int* __restrict__ row,
                          const int* __restrict__ col, int e)
{
    int g = blockIdx.x * blockDim.x + threadIdx.x;
    int eid = g >> 4;
    if (eid >= e) return;
    int l = g & 15;

    float v = __ldg(&val[eid]);
    int r = __ldg(&row[eid]);
    int c = __ldg(&col[eid]);

    float4 zv = reinterpret_cast<const float4*>(g_z)[c * 16 + l];
    float ax = v * zv.x, ay = v * zv.y, az = v * zv.z, aw = v * zv.w;
    float* dst = g_h + (size_t)r * DDIM + l * 4;
    asm volatile("red.global.add.v4.f32 [%0], {%1,%2,%3,%4};"
                 :: "l"(dst), "f"(ax), "f"(ay), "f"(az), "f"(aw) : "memory");
}

// ---------------------------------------------------------------------------
// K4: per-column sum and sum-of-squares of h
// ---------------------------------------------------------------------------
__global__ void __launch_bounds__(256) k_stats(int n)
{
    int cg = threadIdx.x & 15;                 // column group (4 cols)
    float4 s  = make_float4(0.f, 0.f, 0.f, 0.f);
    float4 ss = make_float4(0.f, 0.f, 0.f, 0.f);
    const float4* h4 = reinterpret_cast<const float4*>(g_h);
    int total = n * 16;
    int stride = gridDim.x * blockDim.x;       // multiple of 16 -> cg invariant
    for (int idx = blockIdx.x * blockDim.x + threadIdx.x; idx < total; idx += stride) {
        float4 v = h4[idx];
        s.x += v.x; s.y += v.y; s.z += v.z; s.w += v.w;
        ss.x += v.x * v.x; ss.y += v.y * v.y; ss.z += v.z * v.z; ss.w += v.w * v.w;
    }
    __shared__ float4 sh_s[256];
    __shared__ float4 sh_q[256];
    sh_s[threadIdx.x] = s;
    sh_q[threadIdx.x] = ss;
    __syncthreads();
#pragma unroll
    for (int off = 128; off >= 16; off >>= 1) {
        if (threadIdx.x < off) {
            float4 a = sh_s[threadIdx.x], b = sh_s[threadIdx.x + off];
            a.x += b.x; a.y += b.y; a.z += b.z; a.w += b.w;
            sh_s[threadIdx.x] = a;
            float4 c = sh_q[threadIdx.x], d = sh_q[threadIdx.x + off];
            c.x += d.x; c.y += d.y; c.z += d.z; c.w += d.w;
            sh_q[threadIdx.x] = c;
        }
        __syncthreads();
    }
    if (threadIdx.x < 16) {
        float4 a = sh_s[threadIdx.x];
        float4 c = sh_q[threadIdx.x];
        int d0 = cg * 4;
        atomicAdd(&g_sum[d0 + 0], a.x);  atomicAdd(&g_sum[d0 + 1], a.y);
        atomicAdd(&g_sum[d0 + 2], a.z);  atomicAdd(&g_sum[d0 + 3], a.w);
        atomicAdd(&g_sumsq[d0 + 0], c.x); atomicAdd(&g_sumsq[d0 + 1], c.y);
        atomicAdd(&g_sumsq[d0 + 2], c.z); atomicAdd(&g_sumsq[d0 + 3], c.w);
    }
}

// ---------------------------------------------------------------------------
// K5: out = relu((h - mean) * rsqrt(var+eps) * gamma + beta)
//     (scale/shift recomputed per block from the 64 global sums — cheap)
// ---------------------------------------------------------------------------
__global__ void k_norm(const float* __restrict__ gamma,
                       const float* __restrict__ beta,
                       float* __restrict__ out, int n)
{
    __shared__ float sc[DDIM];
    __shared__ float sh[DDIM];
    if (threadIdx.x < DDIM) {
        int d = threadIdx.x;
        float inv = 1.0f / (float)n;
        float mean = g_sum[d] * inv;
        float var  = g_sumsq[d] * inv - mean * mean;
        float s = gamma[d] * rsqrtf(var + EPS_BN);
        sc[d] = s;
        sh[d] = beta[d] - mean * s;
    }
    __syncthreads();
    int idx = blockIdx.x * blockDim.x + threadIdx.x;
    int total = n * 16;
    if (idx < total) {
        float4 v = reinterpret_cast<const float4*>(g_h)[idx];
        int d0 = (idx & 15) * 4;
        float4 o;
        o.x = fmaxf(v.x * sc[d0 + 0] + sh[d0 + 0], 0.f);
        o.y = fmaxf(v.y * sc[d0 + 1] + sh[d0 + 1], 0.f);
        o.z = fmaxf(v.z * sc[d0 + 2] + sh[d0 + 2], 0.f);
        o.w = fmaxf(v.w * sc[d0 + 3] + sh[d0 + 3], 0.f);
        reinterpret_cast<float4*>(out)[idx] = o;
    }
}

// ---------------------------------------------------------------------------
// Launch: inputs in metadata order:
//   0 x [N*64] f32, 1 adj_val [E] f32, 2 W [64*64] f32, 3 b [64] f32,
//   4 gamma [64] f32, 5 beta [64] f32, 6 adj_row [E] i32, 7 adj_col [E] i32
// ---------------------------------------------------------------------------
extern "C" void kernel_launch(void* const* d_in, const int* in_sizes, int n_in,
                              void* d_out, int out_size)
{
    const float* x       = (const float*)d_in[0];
    const float* adj_val = (const float*)d_in[1];
    const float* W       = (const float*)d_in[2];
    const float* b       = (const float*)d_in[3];
    const float* gamma   = (const float*)d_in[4];
    const float* beta    = (const float*)d_in[5];
    const int*   adj_row = (const int*)d_in[6];
    const int*   adj_col = (const int*)d_in[7];
    float* out = (float*)d_out;

    int n = in_sizes[0] / DDIM;    // 100000
    int e = in_sizes[1];           // 1600000
    int nv = n * (DDIM / 4);       // float4 count

    k_init   <<<(nv + 255) / 256, 256>>>(x, b, n);
    k_gemm   <<<(n + 127) / 128, 128>>>(x, W, n);
    k_scatter<<<((long)e * 16 + 255) / 256, 256>>>(adj_val, adj_row, adj_col, e);
    k_stats  <<<1184, 256>>>(n);
    k_norm   <<<(nv + 255) / 256, 256>>>(gamma, beta, out, n);
}

// round 9
// speedup vs baseline: 1.0109x; 1.0009x over previous
#include <cuda_runtime.h>
#include <cstdint>

// Problem constants (shapes are fixed by the dataset; runtime n/e still honored)
#define NMAX 100000
#define DDIM 64
#define EPS_BN 1e-5f

// Scratch (device globals: no allocation allowed in kernel_launch)
__device__ float g_z[NMAX * DDIM];   // z = x @ W^T
__device__ float g_h[NMAX * DDIM];   // h = x + b + A @ z   (pre-BN activations)
__device__ float g_sum[DDIM];
__device__ float g_sumsq[DDIM];

// ---------------------------------------------------------------------------
// K1: h = x + b (fold residual + bias); also zero the BN stat accumulators
// ---------------------------------------------------------------------------
__global__ void k_init(const float* __restrict__ x, const float* __restrict__ b, int n)
{
    if (blockIdx.x == 0 && threadIdx.x < 2 * DDIM) {
        if (threadIdx.x < DDIM) g_sum[threadIdx.x] = 0.f;
        else                    g_sumsq[threadIdx.x - DDIM] = 0.f;
    }
    int idx = blockIdx.x * blockDim.x + threadIdx.x;   // over n*16 float4
    int total = n * (DDIM / 4);
    if (idx < total) {
        float4 xv = reinterpret_cast<const float4*>(x)[idx];
        int d0 = (idx & 15) * 4;
        float4 hv;
        hv.x = xv.x + b[d0 + 0];
        hv.y = xv.y + b[d0 + 1];
        hv.z = xv.z + b[d0 + 2];
        hv.w = xv.w + b[d0 + 3];
        reinterpret_cast<float4*>(g_h)[idx] = hv;
    }
}

// ---------------------------------------------------------------------------
// K2: z = x @ W^T.  One thread per row; W (16KB) in smem, broadcast LDS.128.
// ---------------------------------------------------------------------------
__global__ void __launch_bounds__(128) k_gemm(const float* __restrict__ x,
                                              const float* __restrict__ W, int n)
{
    __shared__ float4 Ws[DDIM * 16];            // W[o][k] as float4 over k
    for (int i = threadIdx.x; i < DDIM * 16; i += 128)
        Ws[i] = reinterpret_cast<const float4*>(W)[i];
    __syncthreads();

    int row = blockIdx.x * 128 + threadIdx.x;
    if (row >= n) return;

    const float4* x4 = reinterpret_cast<const float4*>(x);
    float4 xr[16];
#pragma unroll
    for (int i = 0; i < 16; i++) xr[i] = x4[row * 16 + i];

    float4* z4 = reinterpret_cast<float4*>(g_z);
#pragma unroll 1
    for (int og = 0; og < 16; og++) {          // 4 output columns per iter
        float4 acc = make_float4(0.f, 0.f, 0.f, 0.f);
#pragma unroll
        for (int k4 = 0; k4 < 16; k4++) {
            float4 xv = xr[k4];
            float4 w0 = Ws[(4 * og + 0) * 16 + k4];
            float4 w1 = Ws[(4 * og + 1) * 16 + k4];
            float4 w2 = Ws[(4 * og + 2) * 16 + k4];
            float4 w3 = Ws[(4 * og + 3) * 16 + k4];
            acc.x += xv.x * w0.x + xv.y * w0.y + xv.z * w0.z + xv.w * w0.w;
            acc.y += xv.x * w1.x + xv.y * w1.y + xv.z * w1.z + xv.w * w1.w;
            acc.z += xv.x * w2.x + xv.y * w2.y + xv.z * w2.z + xv.w * w2.w;
            acc.w += xv.x * w3.x + xv.y * w3.y + xv.z * w3.z + xv.w * w3.w;
        }
        z4[row * 16 + og] = acc;
    }
}

// ---------------------------------------------------------------------------
// K3: edge scatter  h[row] += val * z[col]   (16 threads per edge, red.v4.f32)
// ---------------------------------------------------------------------------
__global__ void k_scatter(const float* __restrict__ val,
                          const int* __restrict__ row,
                          const int* __restrict__ col, int e)
{
    int g = blockIdx.x * blockDim.x + threadIdx.x;
    int eid = g >> 4;
    if (eid >= e) return;
    int l = g & 15;

    float v = __ldg(&val[eid]);
    int r = __ldg(&row[eid]);
    int c = __ldg(&col[eid]);

    float4 zv = reinterpret_cast<const float4*>(g_z)[c * 16 + l];
    float ax = v * zv.x, ay = v * zv.y, az = v * zv.z, aw = v * zv.w;
    float* dst = g_h + (size_t)r * DDIM + l * 4;
    asm volatile("red.global.add.v4.f32 [%0], {%1,%2,%3,%4};"
                 :: "l"(dst), "f"(ax), "f"(ay), "f"(az), "f"(aw) : "memory");
}

// ---------------------------------------------------------------------------
// K4: per-column sum and sum-of-squares of h
// ---------------------------------------------------------------------------
__global__ void __launch_bounds__(256) k_stats(int n)
{
    int cg = threadIdx.x & 15;                 // column group (4 cols)
    float4 s  = make_float4(0.f, 0.f, 0.f, 0.f);
    float4 ss = make_float4(0.f, 0.f, 0.f, 0.f);
    const float4* h4 = reinterpret_cast<const float4*>(g_h);
    int total = n * 16;
    int stride = gridDim.x * blockDim.x;       // multiple of 16 -> cg invariant
    for (int idx = blockIdx.x * blockDim.x + threadIdx.x; idx < total; idx += stride) {
        float4 v = h4[idx];
        s.x += v.x; s.y += v.y; s.z += v.z; s.w += v.w;
        ss.x += v.x * v.x; ss.y += v.y * v.y; ss.z += v.z * v.z; ss.w += v.w * v.w;
    }
    __shared__ float4 sh_s[256];
    __shared__ float4 sh_q[256];
    sh_s[threadIdx.x] = s;
    sh_q[threadIdx.x] = ss;
    __syncthreads();
#pragma unroll
    for (int off = 128; off >= 16; off >>= 1) {
        if (threadIdx.x < off) {
            float4 a = sh_s[threadIdx.x], b = sh_s[threadIdx.x + off];
            a.x += b.x; a.y += b.y; a.z += b.z; a.w += b.w;
            sh_s[threadIdx.x] = a;
            float4 c = sh_q[threadIdx.x], d = sh_q[threadIdx.x + off];
            c.x += d.x; c.y += d.y; c.z += d.z; c.w += d.w;
            sh_q[threadIdx.x] = c;
        }
        __syncthreads();
    }
    if (threadIdx.x < 16) {
        float4 a = sh_s[threadIdx.x];
        float4 c = sh_q[threadIdx.x];
        int d0 = cg * 4;
        atomicAdd(&g_sum[d0 + 0], a.x);  atomicAdd(&g_sum[d0 + 1], a.y);
        atomicAdd(&g_sum[d0 + 2], a.z);  atomicAdd(&g_sum[d0 + 3], a.w);
        atomicAdd(&g_sumsq[d0 + 0], c.x); atomicAdd(&g_sumsq[d0 + 1], c.y);
        atomicAdd(&g_sumsq[d0 + 2], c.z); atomicAdd(&g_sumsq[d0 + 3], c.w);
    }
}

// ---------------------------------------------------------------------------
// K5: out = relu((h - mean) * rsqrt(var+eps) * gamma + beta)
//     (scale/shift recomputed per block from the 64 global sums — cheap)
// ---------------------------------------------------------------------------
__global__ void k_norm(const float* __restrict__ gamma,
                       const float* __restrict__ beta,
                       float* __restrict__ out, int n)
{
    __shared__ float sc[DDIM];
    __shared__ float sh[DDIM];
    if (threadIdx.x < DDIM) {
        int d = threadIdx.x;
        float inv = 1.0f / (float)n;
        float mean = g_sum[d] * inv;
        float var  = g_sumsq[d] * inv - mean * mean;
        float s = gamma[d] * rsqrtf(var + EPS_BN);
        sc[d] = s;
        sh[d] = beta[d] - mean * s;
    }
    __syncthreads();
    int idx = blockIdx.x * blockDim.x + threadIdx.x;
    int total = n * 16;
    if (idx < total) {
        float4 v = reinterpret_cast<const float4*>(g_h)[idx];
        int d0 = (idx & 15) * 4;
        float4 o;
        o.x = fmaxf(v.x * sc[d0 + 0] + sh[d0 + 0], 0.f);
        o.y = fmaxf(v.y * sc[d0 + 1] + sh[d0 + 1], 0.f);
        o.z = fmaxf(v.z * sc[d0 + 2] + sh[d0 + 2], 0.f);
        o.w = fmaxf(v.w * sc[d0 + 3] + sh[d0 + 3], 0.f);
        reinterpret_cast<float4*>(out)[idx] = o;
    }
}

// ---------------------------------------------------------------------------
// Launch: inputs in metadata order:
//   0 x [N*64] f32, 1 adj_val [E] f32, 2 W [64*64] f32, 3 b [64] f32,
//   4 gamma [64] f32, 5 beta [64] f32, 6 adj_row [E] i32, 7 adj_col [E] i32
// ---------------------------------------------------------------------------
extern "C" void kernel_launch(void* const* d_in, const int* in_sizes, int n_in,
                              void* d_out, int out_size)
{
    const float* x       = (const float*)d_in[0];
    const float* adj_val = (const float*)d_in[1];
    const float* W       = (const float*)d_in[2];
    const float* b       = (const float*)d_in[3];
    const float* gamma   = (const float*)d_in[4];
    const float* beta    = (const float*)d_in[5];
    const int*   adj_row = (const int*)d_in[6];
    const int*   adj_col = (const int*)d_in[7];
    float* out = (float*)d_out;

    int n = in_sizes[0] / DDIM;    // 100000
    int e = in_sizes[1];           // 1600000
    int nv = n * (DDIM / 4);       // float4 count

    k_init   <<<(nv + 255) / 256, 256>>>(x, b, n);
    k_gemm   <<<(n + 127) / 128, 128>>>(x, W, n);
    k_scatter<<<((long)e * 16 + 255) / 256, 256>>>(adj_val, adj_row, adj_col, e);
    k_stats  <<<1184, 256>>>(n);
    k_norm   <<<(nv + 255) / 256, 256>>>(gamma, beta, out, n);
}